// round 15
// baseline (speedup 1.0000x reference)
#include <cuda_runtime.h>
#include <cuda_fp16.h>

// WormnetCell: liquid time-constant cell, semi-implicit ODE, 6 unfolds.
// BATCH=8192 rows, U=128 units, IN=32 sensory inputs.
//
// R12: R11's plateau = FMA pipe binding (3 FFMA/synapse >= XU time).
//  - fma.rn.f32x2 dual-accumulation: (num,den) packed f32x2, (we,w) packed
//    once per i-step -> per synapse 1 FFMA(arg) + 1 MOV64(dup th) + 1 FFMA2.
//    FMA pipe 3 ops -> 2 ops per synapse; bit-exact IEEE fma per lane.
//  - TSPLIT 28 -> 32 (XU becomes sole binder again)
//  - direct __ldg (no prefetch regs; params L1-hot), lb(128,7) single wave
// Table path (i < TSPLIT): smem tanh table, nearest entry, 3072 x f32 on
// [-6,6]; arg FFMA (1/h folded) -> clamp -> +2^23 magic -> mask -> LDS.32.

#define UDIM 128
#define INDIM 32
#define RPB 8
#define NUNFOLDS 6

#define TSPLIT 32              // units evaluated via smem table
#define TABN 3072              // table entries
#define TAB_INVH 256.0f        // 1/h  (h = 12/3072 = 1/256)
#define TAB_OFF 1536.0f        // 6/h  (arg -6 maps to index 0)
#define FMAGIC 8388608.0f      // 2^23

typedef unsigned long long u64;

// Packed per-synapse params:
//  i <  TSPLIT: {a/h, nb/h + TAB_OFF, we, w}   (table-unit form)
//  i >= TSPLIT: {a,   nb,             we, w}   (a = 0.5*sigma, nb = -0.5*sigma*mu)
//  we = 0.5*W*erev, w = 0.5*W
__device__ float4 g_Prec[UDIM * UDIM];
__device__ float4 g_Psen[INDIM * UDIM];
// Per-unit constant halves (sum of we / w over all 160 inputs)
__device__ float  g_Cnum[UDIM];
__device__ float  g_Cden[UDIM];

__device__ __forceinline__ float tanh_fast(float x) {
    float y; asm("tanh.approx.f32 %0, %1;" : "=f"(y) : "f"(x)); return y;
}
__device__ __forceinline__ u64 ffma2(u64 a, u64 b, u64 c) {
    u64 d; asm("fma.rn.f32x2 %0, %1, %2, %3;" : "=l"(d) : "l"(a), "l"(b), "l"(c)); return d;
}
__device__ __forceinline__ u64 pack2(float lo, float hi) {
    u64 r; asm("mov.b64 %0, {%1, %2};" : "=l"(r) : "f"(lo), "f"(hi)); return r;
}
__device__ __forceinline__ float2 unpack2(u64 v) {
    float2 f; asm("mov.b64 {%0, %1}, %2;" : "=f"(f.x), "=f"(f.y) : "l"(v)); return f;
}

// One block per unit-column j (128 blocks x 160 threads).
__global__ void prep_kernel(const float* __restrict__ mu, const float* __restrict__ sig,
                            const float* __restrict__ W, const float* __restrict__ erev,
                            const float* __restrict__ smu, const float* __restrict__ ssig,
                            const float* __restrict__ sW, const float* __restrict__ serev)
{
    __shared__ float sn[UDIM + INDIM];
    __shared__ float sd[UDIM + INDIM];
    const int j = blockIdx.x;
    const int i = threadIdx.x;

    float we, w;
    if (i < UDIM) {
        int idx = i * UDIM + j;
        float a  = 0.5f * sig[idx];
        float nb = -a * mu[idx];
        w  = 0.5f * W[idx];
        we = w * erev[idx];
        if (i < TSPLIT)
            g_Prec[idx] = make_float4(a * TAB_INVH, nb * TAB_INVH + TAB_OFF, we, w);
        else
            g_Prec[idx] = make_float4(a, nb, we, w);
    } else {
        int idx = (i - UDIM) * UDIM + j;
        float a = 0.5f * ssig[idx];
        w  = 0.5f * sW[idx];
        we = w * serev[idx];
        g_Psen[idx] = make_float4(a, -a * smu[idx], we, w);
    }
    sn[i] = we;
    sd[i] = w;
    __syncthreads();

    if (i == 0) {
        float cn = 0.f, cd = 0.f;
        #pragma unroll 8
        for (int k = 0; k < UDIM + INDIM; k++) { cn += sn[k]; cd += sd[k]; }
        g_Cnum[j] = cn;
        g_Cden[j] = cd;
    }
}

__global__ void __launch_bounds__(UDIM, 7)
worm_kernel(const float* __restrict__ inputs, const float* __restrict__ state,
            const float* __restrict__ vleak, const float* __restrict__ gleak,
            const float* __restrict__ cm,
            const float* __restrict__ in_w, const float* __restrict__ in_b,
            const float* __restrict__ out_w, const float* __restrict__ out_b,
            float* __restrict__ out_y, float* __restrict__ out_v)
{
    __shared__ __align__(16) float vT[2][UDIM * RPB];   // double-buffered state
    __shared__ __align__(16) float sBn[UDIM * RPB];     // base num per (j, r)
    __shared__ __align__(16) float sBd[UDIM * RPB];     // base den per (j, r)
    __shared__ float xT[INDIM * RPB];
    __shared__ float tab[TABN];                          // tanh table on [-6, 6]

    const int j = threadIdx.x;                           // unit index 0..127
    const long long row0 = (long long)blockIdx.x * RPB;

    // ---- fill tanh table (24 entries/thread) ----
    #pragma unroll
    for (int k = j; k < TABN; k += UDIM)
        tab[k] = tanh_fast((float)k * (1.0f / TAB_INVH) - 6.0f);

    // ---- state -> vT[0] ----
    #pragma unroll
    for (int r = 0; r < RPB; r++)
        vT[0][j * RPB + r] = state[(row0 + r) * UDIM + j];

    // ---- inputs with affine map ----
    #pragma unroll
    for (int k = 0; k < (INDIM * RPB) / UDIM; k++) {
        int idx = k * UDIM + j;
        int r = idx / INDIM, i = idx % INDIM;
        xT[i * RPB + r] = fmaf(inputs[(row0 + r) * INDIM + i], __ldg(&in_w[i]), __ldg(&in_b[i]));
    }
    __syncthreads();

    // ---- sensory contribution (fixed across unfolds) + constant halves -> smem ----
    {
        float bnum[RPB], bden[RPB];
        float c0 = g_Cnum[j], d0 = g_Cden[j];
        #pragma unroll
        for (int r = 0; r < RPB; r++) { bnum[r] = c0; bden[r] = d0; }

        #pragma unroll 4
        for (int i = 0; i < INDIM; i++) {
            float4 p = __ldg(&g_Psen[i * UDIM + j]);
            const float4* xp = reinterpret_cast<const float4*>(&xT[i * RPB]);
            float4 x0 = xp[0], x1 = xp[1];
            float xv[RPB] = {x0.x, x0.y, x0.z, x0.w, x1.x, x1.y, x1.z, x1.w};
            #pragma unroll
            for (int r = 0; r < RPB; r++) {
                float th = tanh_fast(fmaf(p.x, xv[r], p.y));
                bnum[r] = fmaf(p.z, th, bnum[r]);
                bden[r] = fmaf(p.w, th, bden[r]);
            }
        }
        #pragma unroll
        for (int r = 0; r < RPB; r++) {
            sBn[j * RPB + r] = bnum[r];
            sBd[j * RPB + r] = bden[r];
        }
    }

    const float cmj = cm[j];
    const float glj = gleak[j];
    const float gvj = glj * vleak[j];
    const float cgj = cmj + glj;

    #pragma unroll 1
    for (int t = 0; t < NUNFOLDS; t++) {
        const int cur = t & 1, nxt = cur ^ 1;
        const float* __restrict__ vc = vT[cur];

        // f32x2 accumulators: lanes = (num, den)
        u64 nd[RPB];
        #pragma unroll
        for (int r = 0; r < RPB; r++)
            nd[r] = pack2(sBn[j * RPB + r], sBd[j * RPB + r]);

        // ===== units 0..TSPLIT-1: smem tanh table (no XU) =====
        #pragma unroll 2
        for (int i = 0; i < TSPLIT; i++) {
            const float4 p = __ldg(&g_Prec[i * UDIM + j]);
            const u64 wew = pack2(p.z, p.w);             // (we, w) once per i-step
            const float4* vp = reinterpret_cast<const float4*>(&vc[i * RPB]);
            float4 v0 = vp[0], v1 = vp[1];               // broadcast LDS.128
            float vv[RPB] = {v0.x, v0.y, v0.z, v0.w, v1.x, v1.y, v1.z, v1.w};
            #pragma unroll
            for (int r = 0; r < RPB; r++) {
                float u  = fmaf(p.x, vv[r], p.y);        // arg in table units
                u = fminf(fmaxf(u, 0.0f), (float)(TABN - 1));
                float mg = u + FMAGIC;                   // round-to-nearest in mantissa
                int idx  = __float_as_int(mg) & 0x0FFF;  // TABN-1 = 0xBFF fits
                float th = tab[idx];
                nd[r] = ffma2(wew, pack2(th, th), nd[r]);
            }
        }

        // ===== units TSPLIT..127: MUFU.TANH path =====
        #pragma unroll 2
        for (int i = TSPLIT; i < UDIM; i++) {
            const float4 p = __ldg(&g_Prec[i * UDIM + j]);
            const u64 wew = pack2(p.z, p.w);
            const float4* vp = reinterpret_cast<const float4*>(&vc[i * RPB]);
            float4 v0 = vp[0], v1 = vp[1];               // broadcast LDS.128
            float vv[RPB] = {v0.x, v0.y, v0.z, v0.w, v1.x, v1.y, v1.z, v1.w};
            #pragma unroll
            for (int r = 0; r < RPB; r++) {
                float th = tanh_fast(fmaf(p.x, vv[r], p.y));
                nd[r] = ffma2(wew, pack2(th, th), nd[r]);
            }
        }

        // old v (own slots) from current buffer
        float vold[RPB];
        {
            const float4* vo = reinterpret_cast<const float4*>(&vc[j * RPB]);
            float4 a = vo[0], b = vo[1];
            vold[0]=a.x; vold[1]=a.y; vold[2]=a.z; vold[3]=a.w;
            vold[4]=b.x; vold[5]=b.y; vold[6]=b.z; vold[7]=b.w;
        }

        float vn[RPB];
        #pragma unroll
        for (int r = 0; r < RPB; r++) {
            float2 f = unpack2(nd[r]);                   // (num, den)
            vn[r] = __fdividef(fmaf(cmj, vold[r], gvj + f.x), cgj + f.y);
        }

        float4* vw = reinterpret_cast<float4*>(&vT[nxt][j * RPB]);
        vw[0] = make_float4(vn[0], vn[1], vn[2], vn[3]);
        vw[1] = make_float4(vn[4], vn[5], vn[6], vn[7]);

        __syncthreads();
    }

    // ---- outputs: final state sits in vT[NUNFOLDS & 1] ----
    const float* vf = vT[NUNFOLDS & 1];
    if (out_v) {
        #pragma unroll
        for (int r = 0; r < RPB; r++)
            out_v[(row0 + r) * UDIM + j] = vf[j * RPB + r];
    }
    if (out_y && j == 0) {
        float ow = __ldg(&out_w[0]), ob = __ldg(&out_b[0]);
        #pragma unroll
        for (int r = 0; r < RPB; r++)
            out_y[row0 + r] = fmaf(vf[r], ow, ob);       // j == 0 -> slots 0..7
    }
}

extern "C" void kernel_launch(void* const* d_in, const int* in_sizes, int n_in,
                              void* d_out, int out_size)
{
    const float* inputs = (const float*)d_in[0];
    const float* state  = (const float*)d_in[1];
    const float* smu    = (const float*)d_in[2];
    const float* ssig   = (const float*)d_in[3];
    const float* sW     = (const float*)d_in[4];
    const float* serev  = (const float*)d_in[5];
    const float* mu     = (const float*)d_in[6];
    const float* sig    = (const float*)d_in[7];
    const float* W      = (const float*)d_in[8];
    const float* erev   = (const float*)d_in[9];
    const float* vleak  = (const float*)d_in[10];
    const float* gleak  = (const float*)d_in[11];
    const float* cm     = (const float*)d_in[12];
    const float* in_w   = (const float*)d_in[13];
    const float* in_b   = (const float*)d_in[14];
    const float* out_w  = (const float*)d_in[15];
    const float* out_b  = (const float*)d_in[16];

    const int batch = in_sizes[1] / UDIM;   // 8192

    float* out   = (float*)d_out;
    float* out_y = nullptr;
    float* out_v = nullptr;
    if (out_size == batch + batch * UDIM) {       // (outputs, v) concatenated
        out_y = out;
        out_v = out + batch;
    } else if (out_size == batch * UDIM) {        // v only
        out_v = out;
    } else {                                      // outputs only
        out_y = out;
    }

    prep_kernel<<<UDIM, UDIM + INDIM>>>(mu, sig, W, erev, smu, ssig, sW, serev);
    worm_kernel<<<batch / RPB, UDIM>>>(inputs, state, vleak, gleak, cm,
                                       in_w, in_b, out_w, out_b, out_y, out_v);
}